// round 12
// baseline (speedup 1.0000x reference)
#include <cuda_runtime.h>
#include <cuda_bf16.h>
#include <cstdint>

#define TT 256
#define NLSTM 128
#define ACHP 18432                 // A chunk: 128 rows x 144B (data in first 128B)
#define SLOTP (16*ACHP)
#define BCHP 4608                  // W chunk: 32 rows x 144B
#define WCTAP (16*BCHP)
#define FCDP (16*ACHP)

// ------------------------- device scratch -------------------------
__device__ __align__(128) unsigned char g_Ahi[(size_t)(TT+1)*SLOTP];
__device__ __align__(128) unsigned char g_Alo[(size_t)(TT+1)*SLOTP];
__device__ __align__(128) unsigned char g_WsHi[(size_t)NLSTM*WCTAP];
__device__ __align__(128) unsigned char g_WsLo[(size_t)NLSTM*WCTAP];
__device__ __align__(128) unsigned char g_W0Hi[(size_t)NLSTM*WCTAP];
__device__ __align__(128) unsigned char g_W0Lo[(size_t)NLSTM*WCTAP];
__device__ __align__(128) unsigned char g_FcHi[(size_t)8*FCDP];
__device__ __align__(128) unsigned char g_FcLo[(size_t)8*FCDP];
__device__ float g_biasP[NLSTM*32];
__device__ unsigned g_bar;
__device__ unsigned g_fcitem;

// ------------------------- helpers -------------------------
__device__ __forceinline__ uint32_t smem_u32(const void* p) {
    uint32_t a;
    asm("{ .reg .u64 t; cvta.to.shared.u64 t, %1; cvt.u32.u64 %0, t; }" : "=r"(a) : "l"(p));
    return a;
}
__device__ __forceinline__ void cpa16(uint32_t dst, const void* src) {
    asm volatile("cp.async.cg.shared.global [%0], [%1], 16;" :: "r"(dst), "l"(src));
}
#define CP_COMMIT() asm volatile("cp.async.commit_group;")
#define CP_WAIT1()  asm volatile("cp.async.wait_group 1;")
#define CP_WAIT0()  asm volatile("cp.async.wait_group 0;")

__device__ __forceinline__ void hmma(float* c, const uint32_t* a, uint32_t b0, uint32_t b1) {
    asm volatile(
        "mma.sync.aligned.m16n8k16.row.col.f32.bf16.bf16.f32 "
        "{%0,%1,%2,%3}, {%4,%5,%6,%7}, {%8,%9}, {%0,%1,%2,%3};"
        : "+f"(c[0]), "+f"(c[1]), "+f"(c[2]), "+f"(c[3])
        : "r"(a[0]), "r"(a[1]), "r"(a[2]), "r"(a[3]), "r"(b0), "r"(b1));
}
__device__ __forceinline__ float sigf(float x)  { return 1.0f / (1.0f + __expf(-x)); }
__device__ __forceinline__ float tanhx(float x) { return 2.0f / (1.0f + __expf(-2.0f * x)) - 1.0f; }

// Row layout (64 k-elements per 144B row, data in first 128B), pair-interleaved:
// k-local kl: ks=kl>>4, j=kl&15, half=j>>3, p=j&7, word t=p>>1, elt b=p&1
//   byte_off = ks*32 + t*8 + half*4 + b*2
// -> thread (tig) reads its two k-half fragments of one ks as ONE aligned uint2.

// pack8: 8 consecutive k elements (one old 16B unit) -> 4 words scattered at +t*8
__device__ __forceinline__ void scat8(float* v, unsigned char* hi, unsigned char* lo, size_t off) {
#pragma unroll
    for (int t = 0; t < 4; t++) {
        __nv_bfloat16 h0 = __float2bfloat16(v[2*t]);
        __nv_bfloat16 h1 = __float2bfloat16(v[2*t+1]);
        __nv_bfloat162 ph = __halves2bfloat162(h0, h1);
        __nv_bfloat162 pl = __halves2bfloat162(
            __float2bfloat16(v[2*t]   - __bfloat162float(h0)),
            __float2bfloat16(v[2*t+1] - __bfloat162float(h1)));
        *(uint32_t*)(hi + off + t*8) = *(uint32_t*)&ph;
        *(uint32_t*)(lo + off + t*8) = *(uint32_t*)&pl;
    }
}

// ------------------------- prep -------------------------
__global__ void prep(const float* __restrict__ hT, const float* __restrict__ Wih,
                     const float* __restrict__ Whh, const float* __restrict__ bih,
                     const float* __restrict__ bhh, const float* __restrict__ Wfc)
{
    size_t idx = (size_t)blockIdx.x * blockDim.x + threadIdx.x;
    size_t str = (size_t)gridDim.x * blockDim.x;
    if (idx == 0) { g_bar = 0; g_fcitem = 0; }

    // step weights: cta(128) x np(32) x kg(128 groups of 8)
    for (size_t i = idx; i < (size_t)524288; i += str) {
        int kg = (int)(i & 127), np = (int)((i >> 7) & 31), cta = (int)(i >> 12);
        int row = (np & 3) * 1024 + cta * 8 + (np >> 2);
        int k = kg * 8;
        float wi[8], ws[8];
#pragma unroll
        for (int e = 0; e < 8; e++) {
            float a = Wih[(size_t)row * 1024 + k + e];
            wi[e] = a; ws[e] = a + Whh[(size_t)row * 1024 + k + e];
        }
        int u = kg & 7;
        size_t base = (size_t)cta * WCTAP + (size_t)(kg >> 3) * BCHP
                    + np * 144 + (u >> 1) * 32 + (u & 1) * 4;
        scat8(wi, g_W0Hi, g_W0Lo, base);
        scat8(ws, g_WsHi, g_WsLo, base);
    }
    // fc weights: dt(8) x np(128) x kg(128)
    for (size_t i = idx; i < (size_t)131072; i += str) {
        int kg = (int)(i & 127), np = (int)((i >> 7) & 127), dt = (int)(i >> 14);
        float w[8];
#pragma unroll
        for (int e = 0; e < 8; e++) w[e] = Wfc[(size_t)(dt * 128 + np) * 1024 + kg * 8 + e];
        int u = kg & 7;
        size_t base = (size_t)dt * FCDP + (size_t)(kg >> 3) * ACHP
                    + np * 144 + (u >> 1) * 32 + (u & 1) * 4;
        scat8(w, g_FcHi, g_FcLo, base);
    }
    // hT -> slot 0
    for (size_t i = idx; i < (size_t)16384; i += str) {
        int kg = (int)(i & 127), m = (int)(i >> 7);
        float v[8];
#pragma unroll
        for (int e = 0; e < 8; e++) v[e] = hT[(size_t)m * 1024 + kg * 8 + e];
        int u = kg & 7;
        size_t base = (size_t)(kg >> 3) * ACHP + m * 144 + (u >> 1) * 32 + (u & 1) * 4;
        scat8(v, g_Ahi, g_Alo, base);
    }
    for (size_t i = idx; i < (size_t)4096; i += str) {
        int np = (int)(i & 31), cta = (int)(i >> 5);
        int row = (np & 3) * 1024 + cta * 8 + (np >> 2);
        g_biasP[i] = bih[row] + bhh[row];
    }
}

// ------------------------- fused persistent kernel -------------------------
#define W_LO   73728
#define ABUF   147456
#define WBUF   9216               // per-warp staging (2 x 4608: Ahi 2304 | Alo 2304)
#define S_BIAS 221184
#define S_ITEM 221312
#define SM_ALL 221440

__global__ void __launch_bounds__(256, 1) lstm_fused(const float* __restrict__ bfc,
                                                     float* __restrict__ out)
{
    extern __shared__ unsigned char smem[];
    const uint32_t sb = smem_u32(smem);
    const int tid = threadIdx.x;
    const int w = tid >> 5, lane = tid & 31;
    const int g = lane >> 2, tig = lane & 3;
    const int cta = blockIdx.x;

    if (cta < NLSTM) {
        // ---------------- LSTM role ----------------
        if (tid < 32) ((float*)(smem + S_BIAS))[tid] = g_biasP[cta * 32 + tid];
        const float* biasS = (const float*)(smem + S_BIAS);

        // resident W <- W0 (trimmed: 8 units/row)
        {
            const unsigned char* s2 = g_W0Hi + (size_t)cta * WCTAP;
            const unsigned char* s3 = g_W0Lo + (size_t)cta * WCTAP;
            for (int i = tid; i < 4096; i += 256) {
                int off = (i >> 8) * BCHP + ((i >> 3) & 31) * 144 + (i & 7) * 16;
                cpa16(sb + off, s2 + off);
                cpa16(sb + W_LO + off, s3 + off);
            }
            CP_COMMIT();
            CP_WAIT0();
        }
        __syncthreads();

        float c[4] = {0.f, 0.f, 0.f, 0.f};
        const uint32_t mybuf = sb + ABUF + w * WBUF;
        const int rowoff = 16 * w;

        for (int t = 0; t < TT; t++) {
            if (tid == 0 && t > 0) {
                unsigned tgt = (unsigned)(NLSTM * t), v;
                do {
                    asm volatile("ld.acquire.gpu.global.u32 %0, [%1];" : "=r"(v) : "l"(&g_bar));
                    if ((int)(v - tgt) >= 0) break;
                    __nanosleep(32);
                } while (1);
            }
            __syncthreads();

            const unsigned char* aH = g_Ahi + (size_t)t * SLOTP + (size_t)rowoff * 144;
            const unsigned char* aL = g_Alo + (size_t)t * SLOTP + (size_t)rowoff * 144;

            // per-warp chunk load, padding trimmed: 16 rows x 8 units, hi+lo
            auto issueA = [&](int kc) {
                uint32_t d = mybuf + (kc & 1) * 4608;
                const unsigned char* sA = aH + (size_t)kc * ACHP;
                const unsigned char* sL = aL + (size_t)kc * ACHP;
#pragma unroll
                for (int i = 0; i < 4; i++) {
                    int e = lane + i * 32;                   // 0..127
                    int off = (e >> 3) * 144 + (e & 7) * 16;
                    cpa16(d + off, sA + off);
                }
#pragma unroll
                for (int i = 0; i < 4; i++) {
                    int e = lane + i * 32;
                    int off = (e >> 3) * 144 + (e & 7) * 16;
                    cpa16(d + 2304 + off, sL + off);
                }
                CP_COMMIT();
            };

            float accH[4][4], accX[4][4];
#pragma unroll
            for (int n = 0; n < 4; n++)
#pragma unroll
                for (int q = 0; q < 4; q++) { accH[n][q] = 0.f; accX[n][q] = 0.f; }

            issueA(0); issueA(1);
            for (int kc = 0; kc < 16; kc++) {
                if (kc == 15) CP_WAIT0(); else CP_WAIT1();
                __syncwarp();
                const unsigned char* As = smem + ABUF + w * WBUF + (kc & 1) * 4608;
                const unsigned char* Al = As + 2304;
                const unsigned char* Bh = smem + kc * BCHP;
                const unsigned char* Bl = smem + W_LO + kc * BCHP;
                const int rb = g * 144 + tig * 8;
#pragma unroll
                for (int ks = 0; ks < 4; ks++) {
                    const int ao = rb + ks * 32;
                    uint2 a02 = *(const uint2*)(As + ao);          // ah0, ah2
                    uint2 a13 = *(const uint2*)(As + ao + 1152);   // ah1, ah3
                    uint2 l02 = *(const uint2*)(Al + ao);
                    uint2 l13 = *(const uint2*)(Al + ao + 1152);
                    uint32_t ah[4]  = { a02.x, a13.x, a02.y, a13.y };
                    uint32_t al4[4] = { l02.x, l13.x, l02.y, l13.y };
#pragma unroll
                    for (int nt = 0; nt < 4; nt++) {
                        const int bo = (8 * nt + g) * 144 + tig * 8 + ks * 32;
                        uint2 bh = *(const uint2*)(Bh + bo);
                        uint2 bl = *(const uint2*)(Bl + bo);
                        hmma(accH[nt], ah, bh.x, bh.y);
                        hmma(accX[nt], al4, bh.x, bh.y);
                        hmma(accX[nt], ah, bl.x, bl.y);
                    }
                }
                __syncwarp();
                if (kc + 2 < 16) issueA(kc + 2);
            }

            if (t == 0) {
                __syncthreads();   // all warps done reading W0 before swap
                const unsigned char* s2 = g_WsHi + (size_t)cta * WCTAP;
                const unsigned char* s3 = g_WsLo + (size_t)cta * WCTAP;
                for (int i = tid; i < 4096; i += 256) {
                    int off = (i >> 8) * BCHP + ((i >> 3) & 31) * 144 + (i & 7) * 16;
                    cpa16(sb + off, s2 + off);
                    cpa16(sb + W_LO + off, s3 + off);
                }
                CP_COMMIT();
                CP_WAIT0();
                __syncthreads();
            }

            // epilogue
            const int parity = lane & 1;
#pragma unroll
            for (int nt = 0; nt < 4; nt++) {
                float d0 = accH[nt][0] + accX[nt][0];
                float d1 = accH[nt][1] + accX[nt][1];
                float d2 = accH[nt][2] + accX[nt][2];
                float d3 = accH[nt][3] + accX[nt][3];
                float s0 = parity ? d0 : d2;
                float s1 = parity ? d1 : d3;
                float r0 = __shfl_xor_sync(0xffffffffu, s0, 1);
                float r1 = __shfl_xor_sync(0xffffffffu, s1, 1);
                float ivr, fvr, gvr, ovr; int m;
                if (!parity) { ivr = d0; fvr = d1; gvr = r0; ovr = r1; m = 16 * w + g; }
                else         { ivr = r0; fvr = r1; gvr = d2; ovr = d3; m = 16 * w + g + 8; }
                int u = 2 * nt + (tig >> 1);
                const float* bb = biasS + 4 * u;
                float iv = sigf(ivr + bb[0]);
                float fv = sigf(fvr + bb[1]);
                float gv = tanhx(gvr + bb[2]);
                float ov = sigf(ovr + bb[3]);
                c[nt] = fv * c[nt] + iv * gv;
                float h = ov * tanhx(c[nt]);
                int j = cta * 8 + u;
                int kl = j & 63, jj = kl & 15, p = jj & 7;
                int wroff = (kl >> 4) * 32 + (p >> 1) * 8 + (jj >> 3) * 4 + (p & 1) * 2;
                size_t off = (size_t)(t + 1) * SLOTP + (size_t)(j >> 6) * ACHP
                           + (size_t)m * 144 + wroff;
                __nv_bfloat16 hh = __float2bfloat16(h);
                *(__nv_bfloat16*)(g_Ahi + off) = hh;
                *(__nv_bfloat16*)(g_Alo + off) = __float2bfloat16(h - __bfloat162float(hh));
            }
            __syncthreads();
            if (tid == 0)
                asm volatile("red.release.gpu.global.add.u32 [%0], %1;" :: "l"(&g_bar), "r"(1u) : "memory");
        }
        __syncthreads();
    }

    // ---------------- FC worker role ----------------
    unsigned* itemp = (unsigned*)(smem + S_ITEM);
    for (;;) {
        __syncthreads();
        if (tid == 0) *itemp = atomicAdd(&g_fcitem, 1u);
        __syncthreads();
        unsigned item = *itemp;
        if (item >= 2048u) break;
        int s = (int)(item >> 3), dt = (int)(item & 7);

        if (tid == 0) {
            unsigned tgt = (unsigned)(NLSTM * (s + 1)), v;
            do {
                asm volatile("ld.acquire.gpu.global.u32 %0, [%1];" : "=r"(v) : "l"(&g_bar));
                if ((int)(v - tgt) >= 0) break;
                __nanosleep(64);
            } while (1);
        }
        __syncthreads();

        const unsigned char* aH = g_Ahi + (size_t)(s + 1) * SLOTP;
        const unsigned char* aL = g_Alo + (size_t)(s + 1) * SLOTP;
        const unsigned char* bH = g_FcHi + (size_t)dt * FCDP;
        const unsigned char* bL = g_FcLo + (size_t)dt * FCDP;

        auto issueF = [&](int kc) {
            uint32_t d = sb + (kc & 1) * 73728;
            const unsigned char* s0 = aH + (size_t)kc * ACHP;
            const unsigned char* s1 = aL + (size_t)kc * ACHP;
            const unsigned char* s2 = bH + (size_t)kc * ACHP;
            const unsigned char* s3 = bL + (size_t)kc * ACHP;
            for (int i = tid; i < 1024; i += 256) {
                int off = (i >> 3) * 144 + (i & 7) * 16;
                cpa16(d + off, s0 + off);
                cpa16(d + 18432 + off, s1 + off);
                cpa16(d + 36864 + off, s2 + off);
                cpa16(d + 55296 + off, s3 + off);
            }
            CP_COMMIT();
        };

        float acc[16][4];
#pragma unroll
        for (int n = 0; n < 16; n++)
#pragma unroll
            for (int q = 0; q < 4; q++) acc[n][q] = 0.f;

        issueF(0); issueF(1);
        for (int kc = 0; kc < 16; kc++) {
            if (kc == 15) CP_WAIT0(); else CP_WAIT1();
            __syncthreads();
            const unsigned char* As = smem + (kc & 1) * 73728;
            const unsigned char* Al = As + 18432;
            const unsigned char* Bh = As + 36864;
            const unsigned char* Bl = As + 55296;
            const int rb = (16 * w + g) * 144 + tig * 8;
#pragma unroll
            for (int ks = 0; ks < 4; ks++) {
                const int ao = rb + ks * 32;
                uint2 a02 = *(const uint2*)(As + ao);
                uint2 a13 = *(const uint2*)(As + ao + 1152);
                uint2 l02 = *(const uint2*)(Al + ao);
                uint2 l13 = *(const uint2*)(Al + ao + 1152);
                uint32_t ah[4]  = { a02.x, a13.x, a02.y, a13.y };
                uint32_t al4[4] = { l02.x, l13.x, l02.y, l13.y };
#pragma unroll
                for (int nt = 0; nt < 16; nt++) {
                    const int bo = (8 * nt + g) * 144 + tig * 8 + ks * 32;
                    uint2 bh = *(const uint2*)(Bh + bo);
                    uint2 bl = *(const uint2*)(Bl + bo);
                    hmma(acc[nt], ah, bh.x, bh.y);
                    hmma(acc[nt], al4, bh.x, bh.y);
                    hmma(acc[nt], ah, bl.x, bl.y);
                }
            }
            __syncthreads();
            if (kc + 2 < 16) issueF(kc + 2);
        }

#pragma unroll
        for (int nt = 0; nt < 16; nt++) {
            int d = dt * 128 + 8 * nt + 2 * tig;
            float2 bb = *(const float2*)(bfc + d);
            int n0 = 16 * w + g;
            float2 v0 = make_float2(acc[nt][0] + bb.x, acc[nt][1] + bb.y);
            float2 v1 = make_float2(acc[nt][2] + bb.x, acc[nt][3] + bb.y);
            *(float2*)(out + ((size_t)n0 * TT + s) * 1024 + d) = v0;
            *(float2*)(out + ((size_t)(n0 + 8) * TT + s) * 1024 + d) = v1;
        }
    }
}

// ------------------------- launch -------------------------
extern "C" void kernel_launch(void* const* d_in, const int* in_sizes, int n_in,
                              void* d_out, int out_size)
{
    const float* hT  = (const float*)d_in[0];
    const float* Wih = (const float*)d_in[1];
    const float* Whh = (const float*)d_in[2];
    const float* bih = (const float*)d_in[3];
    const float* bhh = (const float*)d_in[4];
    const float* Wfc = (const float*)d_in[5];
    const float* bfc = (const float*)d_in[6];
    float* out = (float*)d_out;

    static int total = 0;
    if (total == 0) {
        int smc = 148;
        if (cudaDeviceGetAttribute(&smc, cudaDevAttrMultiProcessorCount, 0) != cudaSuccess)
            smc = 148;
        total = smc < 129 ? 129 : (smc > 192 ? 192 : smc);
        cudaFuncSetAttribute(lstm_fused, cudaFuncAttributeMaxDynamicSharedMemorySize, SM_ALL);
    }

    prep<<<1024, 256>>>(hT, Wih, Whh, bih, bhh, Wfc);
    lstm_fused<<<total, 256, SM_ALL>>>(bfc, out);
}

// round 13
// speedup vs baseline: 1.1920x; 1.1920x over previous
#include <cuda_runtime.h>
#include <cuda_bf16.h>
#include <cstdint>

#define TT 256
#define NLSTM 128
#define ACHP 18432                 // padded A chunk: 128 rows x 144B
#define SLOTP (16*ACHP)            // per A slot per matrix
#define BCHP 4608                  // padded W chunk: 32 rows x 144B
#define WCTAP (16*BCHP)            // 73728 per CTA per matrix
#define FCDP (16*ACHP)             // FC W d-tile per matrix

// ------------------------- device scratch -------------------------
__device__ __align__(128) unsigned char g_Ahi[(size_t)(TT+1)*SLOTP];
__device__ __align__(128) unsigned char g_Alo[(size_t)(TT+1)*SLOTP];
__device__ __align__(128) unsigned char g_WsHi[(size_t)NLSTM*WCTAP];
__device__ __align__(128) unsigned char g_WsLo[(size_t)NLSTM*WCTAP];
__device__ __align__(128) unsigned char g_W0Hi[(size_t)NLSTM*WCTAP];
__device__ __align__(128) unsigned char g_W0Lo[(size_t)NLSTM*WCTAP];
__device__ __align__(128) unsigned char g_FcHi[(size_t)8*FCDP];
__device__ __align__(128) unsigned char g_FcLo[(size_t)8*FCDP];
__device__ float g_biasP[NLSTM*32];
__device__ unsigned g_bar;
__device__ unsigned g_fcitem;

// ------------------------- helpers -------------------------
__device__ __forceinline__ uint32_t smem_u32(const void* p) {
    uint32_t a;
    asm("{ .reg .u64 t; cvta.to.shared.u64 t, %1; cvt.u32.u64 %0, t; }" : "=r"(a) : "l"(p));
    return a;
}
__device__ __forceinline__ void cpa16(uint32_t dst, const void* src) {
    asm volatile("cp.async.cg.shared.global [%0], [%1], 16;" :: "r"(dst), "l"(src));
}
#define CP_COMMIT() asm volatile("cp.async.commit_group;")
#define CP_WAIT1()  asm volatile("cp.async.wait_group 1;")
#define CP_WAIT0()  asm volatile("cp.async.wait_group 0;")

__device__ __forceinline__ void hmma(float* c, const uint32_t* a, uint32_t b0, uint32_t b1) {
    asm volatile(
        "mma.sync.aligned.m16n8k16.row.col.f32.bf16.bf16.f32 "
        "{%0,%1,%2,%3}, {%4,%5,%6,%7}, {%8,%9}, {%0,%1,%2,%3};"
        : "+f"(c[0]), "+f"(c[1]), "+f"(c[2]), "+f"(c[3])
        : "r"(a[0]), "r"(a[1]), "r"(a[2]), "r"(a[3]), "r"(b0), "r"(b1));
}
__device__ __forceinline__ float sigf(float x)  { return 1.0f / (1.0f + __expf(-x)); }
__device__ __forceinline__ float tanhx(float x) { return 2.0f / (1.0f + __expf(-2.0f * x)) - 1.0f; }

// A-side pack (UNCHANGED from R8): 8 elems -> contiguous 16B hi + 16B lo
__device__ __forceinline__ void pack8(const float* v, uint4& hi, uint4& lo) {
    __nv_bfloat16 h[8]; float r[8];
#pragma unroll
    for (int e = 0; e < 8; e++) { h[e] = __float2bfloat16(v[e]); r[e] = v[e] - __bfloat162float(h[e]); }
    uint32_t* hw = (uint32_t*)&hi; uint32_t* lw = (uint32_t*)&lo;
#pragma unroll
    for (int q = 0; q < 4; q++) {
        __nv_bfloat162 ph = __halves2bfloat162(h[2*q], h[2*q+1]);
        __nv_bfloat162 pl = __halves2bfloat162(__float2bfloat16(r[2*q]), __float2bfloat16(r[2*q+1]));
        hw[q] = *(uint32_t*)&ph; lw[q] = *(uint32_t*)&pl;
    }
}

// W-side pair layout: unit u=kg&7 (ks=u>>1, half=u&1); word w (elems 2w,2w+1)
// stored at rowbase + ks*32 + w*8 + half*4. Thread tig then reads its two
// B-fragment words (half0/half1 of word tig) as ONE aligned uint2 at ks*32+tig*8.
__device__ __forceinline__ void packW(const float* v, unsigned char* hi, unsigned char* lo,
                                      size_t rowbase, int u) {
    size_t base = rowbase + (size_t)(u >> 1) * 32 + (u & 1) * 4;
#pragma unroll
    for (int t = 0; t < 4; t++) {
        __nv_bfloat16 h0 = __float2bfloat16(v[2*t]);
        __nv_bfloat16 h1 = __float2bfloat16(v[2*t+1]);
        __nv_bfloat162 ph = __halves2bfloat162(h0, h1);
        __nv_bfloat162 pl = __halves2bfloat162(
            __float2bfloat16(v[2*t]   - __bfloat162float(h0)),
            __float2bfloat16(v[2*t+1] - __bfloat162float(h1)));
        *(uint32_t*)(hi + base + t*8) = *(uint32_t*)&ph;
        *(uint32_t*)(lo + base + t*8) = *(uint32_t*)&pl;
    }
}

// ------------------------- prep -------------------------
__global__ void prep(const float* __restrict__ hT, const float* __restrict__ Wih,
                     const float* __restrict__ Whh, const float* __restrict__ bih,
                     const float* __restrict__ bhh, const float* __restrict__ Wfc)
{
    size_t idx = (size_t)blockIdx.x * blockDim.x + threadIdx.x;
    size_t str = (size_t)gridDim.x * blockDim.x;
    if (idx == 0) { g_bar = 0; g_fcitem = 0; }

    // step weights (pair layout)
    for (size_t i = idx; i < (size_t)524288; i += str) {
        int kg = (int)(i & 127), np = (int)((i >> 7) & 31), cta = (int)(i >> 12);
        int row = (np & 3) * 1024 + cta * 8 + (np >> 2);
        int k = kg * 8;
        float wi[8], ws[8];
#pragma unroll
        for (int e = 0; e < 8; e++) {
            float a = Wih[(size_t)row * 1024 + k + e];
            wi[e] = a; ws[e] = a + Whh[(size_t)row * 1024 + k + e];
        }
        size_t rowbase = (size_t)cta * WCTAP + (size_t)(kg >> 3) * BCHP + np * 144;
        packW(wi, g_W0Hi, g_W0Lo, rowbase, kg & 7);
        packW(ws, g_WsHi, g_WsLo, rowbase, kg & 7);
    }
    // fc weights (pair layout)
    for (size_t i = idx; i < (size_t)131072; i += str) {
        int kg = (int)(i & 127), np = (int)((i >> 7) & 127), dt = (int)(i >> 14);
        float w[8];
#pragma unroll
        for (int e = 0; e < 8; e++) w[e] = Wfc[(size_t)(dt * 128 + np) * 1024 + kg * 8 + e];
        size_t rowbase = (size_t)dt * FCDP + (size_t)(kg >> 3) * ACHP + np * 144;
        packW(w, g_FcHi, g_FcLo, rowbase, kg & 7);
    }
    // hT -> slot 0 (A layout UNCHANGED)
    for (size_t i = idx; i < (size_t)16384; i += str) {
        int kg = (int)(i & 127), m = (int)(i >> 7);
        float v[8];
#pragma unroll
        for (int e = 0; e < 8; e++) v[e] = hT[(size_t)m * 1024 + kg * 8 + e];
        size_t base = (size_t)(kg >> 3) * ACHP + m * 144 + (kg & 7) * 16;
        uint4 h4, l4;
        pack8(v, h4, l4);
        *(uint4*)(g_Ahi + base) = h4; *(uint4*)(g_Alo + base) = l4;
    }
    for (size_t i = idx; i < (size_t)4096; i += str) {
        int np = (int)(i & 31), cta = (int)(i >> 5);
        int row = (np & 3) * 1024 + cta * 8 + (np >> 2);
        g_biasP[i] = bih[row] + bhh[row];
    }
}

// ------------------------- fused persistent kernel -------------------------
#define W_LO   73728
#define ABUF   147456
#define WBUF   9216               // per-warp staging (2 x 4608 {Ahi 2304|Alo 2304})
#define S_BIAS 221184
#define S_ITEM 221312
#define SM_ALL 221440

__global__ void __launch_bounds__(256, 1) lstm_fused(const float* __restrict__ bfc,
                                                     float* __restrict__ out)
{
    extern __shared__ unsigned char smem[];
    const uint32_t sb = smem_u32(smem);
    const int tid = threadIdx.x;
    const int w = tid >> 5, lane = tid & 31;
    const int g = lane >> 2, tig = lane & 3;
    const int cta = blockIdx.x;

    if (cta < NLSTM) {
        // ---------------- LSTM role ----------------
        if (tid < 32) ((float*)(smem + S_BIAS))[tid] = g_biasP[cta * 32 + tid];
        const float* biasS = (const float*)(smem + S_BIAS);

        // resident W <- W0
        {
            const unsigned char* s2 = g_W0Hi + (size_t)cta * WCTAP;
            const unsigned char* s3 = g_W0Lo + (size_t)cta * WCTAP;
            for (int i = tid; i < 4608; i += 256) cpa16(sb + i * 16, s2 + i * 16);
            for (int i = tid; i < 4608; i += 256) cpa16(sb + W_LO + i * 16, s3 + i * 16);
            CP_COMMIT();
            CP_WAIT0();
        }
        __syncthreads();

        float c[4] = {0.f, 0.f, 0.f, 0.f};
        const uint32_t mybuf = sb + ABUF + w * WBUF;
        const int rowoff = 16 * w;

        for (int t = 0; t < TT; t++) {
            if (tid == 0 && t > 0) {
                unsigned tgt = (unsigned)(NLSTM * t), v;
                do {
                    asm volatile("ld.acquire.gpu.global.u32 %0, [%1];" : "=r"(v) : "l"(&g_bar));
                    if ((int)(v - tgt) >= 0) break;
                    __nanosleep(32);
                } while (1);
            }
            __syncthreads();

            const unsigned char* aH = g_Ahi + (size_t)t * SLOTP + (size_t)rowoff * 144;
            const unsigned char* aL = g_Alo + (size_t)t * SLOTP + (size_t)rowoff * 144;

            auto issueA = [&](int kc) {
                uint32_t d = mybuf + (kc & 1) * 4608;
                const unsigned char* sA = aH + (size_t)kc * ACHP;
                const unsigned char* sL = aL + (size_t)kc * ACHP;
#pragma unroll
                for (int i = 0; i < 5; i++) {
                    int e = lane + i * 32;
                    if (e < 144) cpa16(d + e * 16, sA + e * 16);
                }
#pragma unroll
                for (int i = 0; i < 5; i++) {
                    int e = lane + i * 32;
                    if (e < 144) cpa16(d + 2304 + e * 16, sL + e * 16);
                }
                CP_COMMIT();
            };

            float accH[4][4], accX[4][4];
#pragma unroll
            for (int n = 0; n < 4; n++)
#pragma unroll
                for (int q = 0; q < 4; q++) { accH[n][q] = 0.f; accX[n][q] = 0.f; }

            issueA(0); issueA(1);
            for (int kc = 0; kc < 16; kc++) {
                if (kc == 15) CP_WAIT0(); else CP_WAIT1();
                __syncwarp();
                const unsigned char* As = smem + ABUF + w * WBUF + (kc & 1) * 4608;
                const unsigned char* Al = As + 2304;
                const unsigned char* Bh = smem + kc * BCHP;
                const unsigned char* Bl = smem + W_LO + kc * BCHP;
                const int rb = g * 144 + tig * 4;
#pragma unroll
                for (int ks = 0; ks < 4; ks++) {
                    const int ao = rb + ks * 32;
                    uint32_t ah[4], al4[4];
                    ah[0] = *(const uint32_t*)(As + ao);
                    ah[1] = *(const uint32_t*)(As + ao + 1152);
                    ah[2] = *(const uint32_t*)(As + ao + 16);
                    ah[3] = *(const uint32_t*)(As + ao + 1168);
                    al4[0] = *(const uint32_t*)(Al + ao);
                    al4[1] = *(const uint32_t*)(Al + ao + 1152);
                    al4[2] = *(const uint32_t*)(Al + ao + 16);
                    al4[3] = *(const uint32_t*)(Al + ao + 1168);
#pragma unroll
                    for (int nt = 0; nt < 4; nt++) {
                        const int bo = (8 * nt + g) * 144 + ks * 32 + tig * 8;  // pair layout
                        uint2 bh = *(const uint2*)(Bh + bo);
                        uint2 bl = *(const uint2*)(Bl + bo);
                        hmma(accH[nt], ah, bh.x, bh.y);
                        hmma(accX[nt], al4, bh.x, bh.y);
                        hmma(accX[nt], ah, bl.x, bl.y);
                    }
                }
                __syncwarp();
                if (kc + 2 < 16) issueA(kc + 2);
            }

            if (t == 0) {
                __syncthreads();   // all warps done with W0 before swap
                const unsigned char* s2 = g_WsHi + (size_t)cta * WCTAP;
                const unsigned char* s3 = g_WsLo + (size_t)cta * WCTAP;
                for (int i = tid; i < 4608; i += 256) cpa16(sb + i * 16, s2 + i * 16);
                for (int i = tid; i < 4608; i += 256) cpa16(sb + W_LO + i * 16, s3 + i * 16);
                CP_COMMIT();
                CP_WAIT0();
                __syncthreads();
            }

            // epilogue (UNCHANGED from R8)
            const int parity = lane & 1;
#pragma unroll
            for (int nt = 0; nt < 4; nt++) {
                float d0 = accH[nt][0] + accX[nt][0];
                float d1 = accH[nt][1] + accX[nt][1];
                float d2 = accH[nt][2] + accX[nt][2];
                float d3 = accH[nt][3] + accX[nt][3];
                float s0 = parity ? d0 : d2;
                float s1 = parity ? d1 : d3;
                float r0 = __shfl_xor_sync(0xffffffffu, s0, 1);
                float r1 = __shfl_xor_sync(0xffffffffu, s1, 1);
                float ivr, fvr, gvr, ovr; int m;
                if (!parity) { ivr = d0; fvr = d1; gvr = r0; ovr = r1; m = 16 * w + g; }
                else         { ivr = r0; fvr = r1; gvr = d2; ovr = d3; m = 16 * w + g + 8; }
                int u = 2 * nt + (tig >> 1);
                const float* bb = biasS + 4 * u;
                float iv = sigf(ivr + bb[0]);
                float fv = sigf(fvr + bb[1]);
                float gv = tanhx(gvr + bb[2]);
                float ov = sigf(ovr + bb[3]);
                c[nt] = fv * c[nt] + iv * gv;
                float h = ov * tanhx(c[nt]);
                int j = cta * 8 + u;
                size_t off = (size_t)(t + 1) * SLOTP + (size_t)(j >> 6) * ACHP
                           + (size_t)m * 144 + (j & 63) * 2;
                __nv_bfloat16 hh = __float2bfloat16(h);
                *(__nv_bfloat16*)(g_Ahi + off) = hh;
                *(__nv_bfloat16*)(g_Alo + off) = __float2bfloat16(h - __bfloat162float(hh));
            }
            __syncthreads();
            if (tid == 0)
                asm volatile("red.release.gpu.global.add.u32 [%0], %1;" :: "l"(&g_bar), "r"(1u) : "memory");
        }
        __syncthreads();
    }

    // ---------------- FC worker role ----------------
    unsigned* itemp = (unsigned*)(smem + S_ITEM);
    for (;;) {
        __syncthreads();
        if (tid == 0) *itemp = atomicAdd(&g_fcitem, 1u);
        __syncthreads();
        unsigned item = *itemp;
        if (item >= 2048u) break;
        int s = (int)(item >> 3), dt = (int)(item & 7);

        if (tid == 0) {
            unsigned tgt = (unsigned)(NLSTM * (s + 1)), v;
            do {
                asm volatile("ld.acquire.gpu.global.u32 %0, [%1];" : "=r"(v) : "l"(&g_bar));
                if ((int)(v - tgt) >= 0) break;
                __nanosleep(64);
            } while (1);
        }
        __syncthreads();

        const unsigned char* aH = g_Ahi + (size_t)(s + 1) * SLOTP;
        const unsigned char* aL = g_Alo + (size_t)(s + 1) * SLOTP;
        const unsigned char* bH = g_FcHi + (size_t)dt * FCDP;
        const unsigned char* bL = g_FcLo + (size_t)dt * FCDP;

        auto issueF = [&](int kc) {
            uint32_t d = sb + (kc & 1) * 73728;
            const unsigned char* s0 = aH + (size_t)kc * ACHP;
            const unsigned char* s1 = aL + (size_t)kc * ACHP;
            const unsigned char* s2 = bH + (size_t)kc * ACHP;
            const unsigned char* s3 = bL + (size_t)kc * ACHP;
            for (int i = tid; i < 1152; i += 256) cpa16(d + i * 16, s0 + i * 16);
            for (int i = tid; i < 1152; i += 256) cpa16(d + 18432 + i * 16, s1 + i * 16);
            for (int i = tid; i < 1152; i += 256) cpa16(d + 36864 + i * 16, s2 + i * 16);
            for (int i = tid; i < 1152; i += 256) cpa16(d + 55296 + i * 16, s3 + i * 16);
            CP_COMMIT();
        };

        float acc[16][4];
#pragma unroll
        for (int n = 0; n < 16; n++)
#pragma unroll
            for (int q = 0; q < 4; q++) acc[n][q] = 0.f;

        issueF(0); issueF(1);
        for (int kc = 0; kc < 16; kc++) {
            if (kc == 15) CP_WAIT0(); else CP_WAIT1();
            __syncthreads();
            const unsigned char* As = smem + (kc & 1) * 73728;
            const unsigned char* Al = As + 18432;
            const unsigned char* Bh = As + 36864;
            const unsigned char* Bl = As + 55296;
            const int rb = (16 * w + g) * 144 + tig * 4;
#pragma unroll
            for (int ks = 0; ks < 4; ks++) {
                const int ao = rb + ks * 32;
                uint32_t ah[4], al4[4];
                ah[0] = *(const uint32_t*)(As + ao);
                ah[1] = *(const uint32_t*)(As + ao + 1152);
                ah[2] = *(const uint32_t*)(As + ao + 16);
                ah[3] = *(const uint32_t*)(As + ao + 1168);
                al4[0] = *(const uint32_t*)(Al + ao);
                al4[1] = *(const uint32_t*)(Al + ao + 1152);
                al4[2] = *(const uint32_t*)(Al + ao + 16);
                al4[3] = *(const uint32_t*)(Al + ao + 1168);
#pragma unroll
                for (int nt = 0; nt < 16; nt++) {
                    const int bo = (8 * nt + g) * 144 + ks * 32 + tig * 8;  // pair layout
                    uint2 bh = *(const uint2*)(Bh + bo);
                    uint2 bl = *(const uint2*)(Bl + bo);
                    hmma(acc[nt], ah, bh.x, bh.y);
                    hmma(acc[nt], al4, bh.x, bh.y);
                    hmma(acc[nt], ah, bl.x, bl.y);
                }
            }
            __syncthreads();
            if (kc + 2 < 16) issueF(kc + 2);
        }

#pragma unroll
        for (int nt = 0; nt < 16; nt++) {
            int d = dt * 128 + 8 * nt + 2 * tig;
            float2 bb = *(const float2*)(bfc + d);
            int n0 = 16 * w + g;
            float2 v0 = make_float2(acc[nt][0] + bb.x, acc[nt][1] + bb.y);
            float2 v1 = make_float2(acc[nt][2] + bb.x, acc[nt][3] + bb.y);
            *(float2*)(out + ((size_t)n0 * TT + s) * 1024 + d) = v0;
            *(float2*)(out + ((size_t)(n0 + 8) * TT + s) * 1024 + d) = v1;
        }
    }
}

// ------------------------- launch -------------------------
extern "C" void kernel_launch(void* const* d_in, const int* in_sizes, int n_in,
                              void* d_out, int out_size)
{
    const float* hT  = (const float*)d_in[0];
    const float* Wih = (const float*)d_in[1];
    const float* Whh = (const float*)d_in[2];
    const float* bih = (const float*)d_in[3];
    const float* bhh = (const float*)d_in[4];
    const float* Wfc = (const float*)d_in[5];
    const float* bfc = (const float*)d_in[6];
    float* out = (float*)d_out;

    static int total = 0;
    if (total == 0) {
        int smc = 148;
        if (cudaDeviceGetAttribute(&smc, cudaDevAttrMultiProcessorCount, 0) != cudaSuccess)
            smc = 148;
        total = smc < 129 ? 129 : (smc > 192 ? 192 : smc);
        cudaFuncSetAttribute(lstm_fused, cudaFuncAttributeMaxDynamicSharedMemorySize, SM_ALL);
    }

    prep<<<1024, 256>>>(hT, Wih, Whh, bih, bhh, Wfc);
    lstm_fused<<<total, 256, SM_ALL>>>(bfc, out);
}

// round 14
// speedup vs baseline: 1.2608x; 1.0577x over previous
#include <cuda_runtime.h>
#include <cuda_bf16.h>
#include <cstdint>

#define TT 256
#define NLSTM 128
#define ACHP 18432                 // padded A chunk: 128 rows x 144B
#define SLOTP (16*ACHP)            // per A slot per matrix
#define BCHP 4608                  // padded W chunk: 32 rows x 144B
#define WCTAP (16*BCHP)            // 73728 per CTA per matrix
#define FCDP (16*ACHP)             // FC W d-tile per matrix

// ------------------------- device scratch -------------------------
__device__ __align__(128) unsigned char g_Ahi[(size_t)(TT+1)*SLOTP];
__device__ __align__(128) unsigned char g_Alo[(size_t)(TT+1)*SLOTP];
__device__ __align__(128) unsigned char g_WsHi[(size_t)NLSTM*WCTAP];
__device__ __align__(128) unsigned char g_WsLo[(size_t)NLSTM*WCTAP];
__device__ __align__(128) unsigned char g_W0Hi[(size_t)NLSTM*WCTAP];
__device__ __align__(128) unsigned char g_W0Lo[(size_t)NLSTM*WCTAP];
__device__ __align__(128) unsigned char g_FcHi[(size_t)8*FCDP];
__device__ __align__(128) unsigned char g_FcLo[(size_t)8*FCDP];
__device__ float g_biasP[NLSTM*32];
__device__ unsigned g_bar;
__device__ unsigned g_fcitem;

// ------------------------- helpers -------------------------
__device__ __forceinline__ uint32_t smem_u32(const void* p) {
    uint32_t a;
    asm("{ .reg .u64 t; cvta.to.shared.u64 t, %1; cvt.u32.u64 %0, t; }" : "=r"(a) : "l"(p));
    return a;
}
__device__ __forceinline__ void cpa16(uint32_t dst, const void* src) {
    asm volatile("cp.async.cg.shared.global [%0], [%1], 16;" :: "r"(dst), "l"(src));
}
#define CP_COMMIT() asm volatile("cp.async.commit_group;")
#define CP_WAIT0()  asm volatile("cp.async.wait_group 0;")

// ---- bulk copy + mbarrier (sm_90 baseline PTX) ----
__device__ __forceinline__ void bulk_g2s(uint32_t dst, const void* src,
                                         uint32_t bytes, uint32_t mbar) {
    asm volatile(
        "cp.async.bulk.shared::cluster.global.mbarrier::complete_tx::bytes [%0], [%1], %2, [%3];"
        :: "r"(dst), "l"(src), "r"(bytes), "r"(mbar) : "memory");
}
#define MB_INIT(m, c) asm volatile("mbarrier.init.shared.b64 [%0], %1;" :: "r"(m), "r"((unsigned)(c)) : "memory")
#define MB_EXPECT(m, b) asm volatile("mbarrier.arrive.expect_tx.shared.b64 _, [%0], %1;" :: "r"(m), "r"((unsigned)(b)) : "memory")
#define MB_WAIT(m, p) do {                                                        \
    asm volatile("{\n\t.reg .pred P;\nWL%=:\n\t"                                  \
      "mbarrier.try_wait.parity.acquire.cta.shared::cta.b64 P, [%0], %1, 0x989680;\n\t" \
      "@P bra.uni WD%=;\n\tbra.uni WL%=;\nWD%=:\n\t}" :: "r"(m), "r"((unsigned)(p)) : "memory"); \
} while (0)
#define FENCE_ASYNC() asm volatile("fence.proxy.async;" ::: "memory")

__device__ __forceinline__ void hmma(float* c, const uint32_t* a, uint32_t b0, uint32_t b1) {
    asm volatile(
        "mma.sync.aligned.m16n8k16.row.col.f32.bf16.bf16.f32 "
        "{%0,%1,%2,%3}, {%4,%5,%6,%7}, {%8,%9}, {%0,%1,%2,%3};"
        : "+f"(c[0]), "+f"(c[1]), "+f"(c[2]), "+f"(c[3])
        : "r"(a[0]), "r"(a[1]), "r"(a[2]), "r"(a[3]), "r"(b0), "r"(b1));
}
__device__ __forceinline__ float sigf(float x)  { return 1.0f / (1.0f + __expf(-x)); }
__device__ __forceinline__ float tanhx(float x) { return 2.0f / (1.0f + __expf(-2.0f * x)) - 1.0f; }

__device__ __forceinline__ void pack8(const float* v, uint4& hi, uint4& lo) {
    __nv_bfloat16 h[8]; float r[8];
#pragma unroll
    for (int e = 0; e < 8; e++) { h[e] = __float2bfloat16(v[e]); r[e] = v[e] - __bfloat162float(h[e]); }
    uint32_t* hw = (uint32_t*)&hi; uint32_t* lw = (uint32_t*)&lo;
#pragma unroll
    for (int q = 0; q < 4; q++) {
        __nv_bfloat162 ph = __halves2bfloat162(h[2*q], h[2*q+1]);
        __nv_bfloat162 pl = __halves2bfloat162(__float2bfloat16(r[2*q]), __float2bfloat16(r[2*q+1]));
        hw[q] = *(uint32_t*)&ph; lw[q] = *(uint32_t*)&pl;
    }
}

// ------------------------- prep (R8 verbatim) -------------------------
__global__ void prep(const float* __restrict__ hT, const float* __restrict__ Wih,
                     const float* __restrict__ Whh, const float* __restrict__ bih,
                     const float* __restrict__ bhh, const float* __restrict__ Wfc)
{
    size_t idx = (size_t)blockIdx.x * blockDim.x + threadIdx.x;
    size_t str = (size_t)gridDim.x * blockDim.x;
    if (idx == 0) { g_bar = 0; g_fcitem = 0; }

    for (size_t i = idx; i < (size_t)524288; i += str) {
        int kg = (int)(i & 127), np = (int)((i >> 7) & 31), cta = (int)(i >> 12);
        int row = (np & 3) * 1024 + cta * 8 + (np >> 2);
        int k = kg * 8;
        float wi[8], ws[8];
#pragma unroll
        for (int e = 0; e < 8; e++) {
            float a = Wih[(size_t)row * 1024 + k + e];
            wi[e] = a; ws[e] = a + Whh[(size_t)row * 1024 + k + e];
        }
        size_t base = (size_t)cta * WCTAP + (size_t)(kg >> 3) * BCHP + np * 144 + (kg & 7) * 16;
        uint4 h4, l4;
        pack8(wi, h4, l4);
        *(uint4*)(g_W0Hi + base) = h4; *(uint4*)(g_W0Lo + base) = l4;
        pack8(ws, h4, l4);
        *(uint4*)(g_WsHi + base) = h4; *(uint4*)(g_WsLo + base) = l4;
    }
    for (size_t i = idx; i < (size_t)131072; i += str) {
        int kg = (int)(i & 127), np = (int)((i >> 7) & 127), dt = (int)(i >> 14);
        float w[8];
#pragma unroll
        for (int e = 0; e < 8; e++) w[e] = Wfc[(size_t)(dt * 128 + np) * 1024 + kg * 8 + e];
        size_t base = (size_t)dt * FCDP + (size_t)(kg >> 3) * ACHP + np * 144 + (kg & 7) * 16;
        uint4 h4, l4;
        pack8(w, h4, l4);
        *(uint4*)(g_FcHi + base) = h4; *(uint4*)(g_FcLo + base) = l4;
    }
    for (size_t i = idx; i < (size_t)16384; i += str) {
        int kg = (int)(i & 127), m = (int)(i >> 7);
        float v[8];
#pragma unroll
        for (int e = 0; e < 8; e++) v[e] = hT[(size_t)m * 1024 + kg * 8 + e];
        size_t base = (size_t)(kg >> 3) * ACHP + m * 144 + (kg & 7) * 16;
        uint4 h4, l4;
        pack8(v, h4, l4);
        *(uint4*)(g_Ahi + base) = h4; *(uint4*)(g_Alo + base) = l4;
    }
    for (size_t i = idx; i < (size_t)4096; i += str) {
        int np = (int)(i & 31), cta = (int)(i >> 5);
        int row = (np & 3) * 1024 + cta * 8 + (np >> 2);
        g_biasP[i] = bih[row] + bhh[row];
    }
}

// ------------------------- fused persistent kernel -------------------------
// LSTM smem: [0,73728) Whi | [73728,147456) Wlo |
//   [147456,221184) per-warp A staging: 8 x {2 x 4608 {Ahi 2304|Alo 2304}}
//   [221184) bias | [221312) 16 warp mbarriers | [221440) 2 FC mbarriers | [221456) item
#define W_LO   73728
#define ABUF   147456
#define WBUF   9216
#define S_BIAS 221184
#define S_MBW  221312
#define S_MBF  221440
#define S_ITEM 221456
#define SM_ALL 221472

__global__ void __launch_bounds__(256, 1) lstm_fused(const float* __restrict__ bfc,
                                                     float* __restrict__ out)
{
    extern __shared__ unsigned char smem[];
    const uint32_t sb = smem_u32(smem);
    const int tid = threadIdx.x;
    const int w = tid >> 5, lane = tid & 31;
    const int g = lane >> 2, tig = lane & 3;
    const int cta = blockIdx.x;

    // init all mbarriers (every CTA, incl. pure-FC ones)
    if (tid == 0) {
        for (int i = 0; i < 16; i++) MB_INIT(sb + S_MBW + i * 8, 1);
        MB_INIT(sb + S_MBF, 1);
        MB_INIT(sb + S_MBF + 8, 1);
        FENCE_ASYNC();
    }
    __syncthreads();

    if (cta < NLSTM) {
        // ---------------- LSTM role ----------------
        if (tid < 32) ((float*)(smem + S_BIAS))[tid] = g_biasP[cta * 32 + tid];
        const float* biasS = (const float*)(smem + S_BIAS);

        // resident W <- W0 (cp.async path, one-time)
        {
            const unsigned char* s2 = g_W0Hi + (size_t)cta * WCTAP;
            const unsigned char* s3 = g_W0Lo + (size_t)cta * WCTAP;
            for (int i = tid; i < 4608; i += 256) cpa16(sb + i * 16, s2 + i * 16);
            for (int i = tid; i < 4608; i += 256) cpa16(sb + W_LO + i * 16, s3 + i * 16);
            CP_COMMIT();
            CP_WAIT0();
        }
        __syncthreads();

        float c[4] = {0.f, 0.f, 0.f, 0.f};
        const uint32_t mybuf = sb + ABUF + w * WBUF;
        const uint32_t mymb  = sb + S_MBW + w * 16;   // 2 barriers: +0, +8
        const int rowoff = 16 * w;
        int aph[2] = {0, 0};

        for (int t = 0; t < TT; t++) {
            if (tid == 0 && t > 0) {
                unsigned tgt = (unsigned)(NLSTM * t), v;
                do {
                    asm volatile("ld.acquire.gpu.global.u32 %0, [%1];" : "=r"(v) : "l"(&g_bar));
                    if ((int)(v - tgt) >= 0) break;
                    __nanosleep(32);
                } while (1);
            }
            __syncthreads();

            // my 16 contiguous rows of slot t
            const unsigned char* aH = g_Ahi + (size_t)t * SLOTP + (size_t)rowoff * 144;
            const unsigned char* aL = g_Alo + (size_t)t * SLOTP + (size_t)rowoff * 144;

            // one warp-chunk = 2 bulk copies (2304B each), lane 0 issues
            auto issueA = [&](int kc) {
                if (lane == 0) {
                    int b = kc & 1;
                    uint32_t mb = mymb + b * 8;
                    uint32_t d = mybuf + b * 4608;
                    MB_EXPECT(mb, 4608);
                    bulk_g2s(d,        aH + (size_t)kc * ACHP, 2304, mb);
                    bulk_g2s(d + 2304, aL + (size_t)kc * ACHP, 2304, mb);
                }
            };

            float acc[4][4];
#pragma unroll
            for (int n = 0; n < 4; n++)
#pragma unroll
                for (int q = 0; q < 4; q++) acc[n][q] = 0.f;

            issueA(0); issueA(1);
            for (int kc = 0; kc < 16; kc++) {
                int b = kc & 1;
                MB_WAIT(mymb + b * 8, aph[b]); aph[b] ^= 1;   // all lanes: acquire
                __syncwarp();
                const unsigned char* As = smem + ABUF + w * WBUF + b * 4608;
                const unsigned char* Al = As + 2304;
                const unsigned char* Bh = smem + kc * BCHP;
                const unsigned char* Bl = smem + W_LO + kc * BCHP;
                const int rb = g * 144 + tig * 4;
#pragma unroll
                for (int ks = 0; ks < 4; ks++) {
                    const int ao = rb + ks * 32;
                    uint32_t ah[4], al4[4];
                    ah[0] = *(const uint32_t*)(As + ao);
                    ah[1] = *(const uint32_t*)(As + ao + 1152);
                    ah[2] = *(const uint32_t*)(As + ao + 16);
                    ah[3] = *(const uint32_t*)(As + ao + 1168);
                    al4[0] = *(const uint32_t*)(Al + ao);
                    al4[1] = *(const uint32_t*)(Al + ao + 1152);
                    al4[2] = *(const uint32_t*)(Al + ao + 16);
                    al4[3] = *(const uint32_t*)(Al + ao + 1168);
#pragma unroll
                    for (int nt = 0; nt < 4; nt++) {
                        const int bo = (8 * nt + g) * 144 + tig * 4 + ks * 32;
                        uint32_t bh0 = *(const uint32_t*)(Bh + bo);
                        uint32_t bh1 = *(const uint32_t*)(Bh + bo + 16);
                        uint32_t bl0 = *(const uint32_t*)(Bl + bo);
                        uint32_t bl1 = *(const uint32_t*)(Bl + bo + 16);
                        hmma(acc[nt], ah, bh0, bh1);
                        hmma(acc[nt], al4, bh0, bh1);
                        hmma(acc[nt], ah, bl0, bl1);
                    }
                }
                __syncwarp();
                if (kc + 2 < 16) issueA(kc + 2);
            }

            if (t == 0) {
                __syncthreads();   // all warps done with W0 before swap
                const unsigned char* s2 = g_WsHi + (size_t)cta * WCTAP;
                const unsigned char* s3 = g_WsLo + (size_t)cta * WCTAP;
                for (int i = tid; i < 4608; i += 256) cpa16(sb + i * 16, s2 + i * 16);
                for (int i = tid; i < 4608; i += 256) cpa16(sb + W_LO + i * 16, s3 + i * 16);
                CP_COMMIT();
                CP_WAIT0();
                __syncthreads();
            }

            // epilogue (R8 verbatim)
            const int parity = lane & 1;
#pragma unroll
            for (int nt = 0; nt < 4; nt++) {
                float d0 = acc[nt][0], d1 = acc[nt][1], d2 = acc[nt][2], d3 = acc[nt][3];
                float s0 = parity ? d0 : d2;
                float s1 = parity ? d1 : d3;
                float r0 = __shfl_xor_sync(0xffffffffu, s0, 1);
                float r1 = __shfl_xor_sync(0xffffffffu, s1, 1);
                float ivr, fvr, gvr, ovr; int m;
                if (!parity) { ivr = d0; fvr = d1; gvr = r0; ovr = r1; m = 16 * w + g; }
                else         { ivr = r0; fvr = r1; gvr = d2; ovr = d3; m = 16 * w + g + 8; }
                int u = 2 * nt + (tig >> 1);
                const float* bb = biasS + 4 * u;
                float iv = sigf(ivr + bb[0]);
                float fv = sigf(fvr + bb[1]);
                float gv = tanhx(gvr + bb[2]);
                float ov = sigf(ovr + bb[3]);
                c[nt] = fv * c[nt] + iv * gv;
                float h = ov * tanhx(c[nt]);
                int j = cta * 8 + u;
                size_t off = (size_t)(t + 1) * SLOTP + (size_t)(j >> 6) * ACHP
                           + (size_t)m * 144 + (j & 63) * 2;
                __nv_bfloat16 hh = __float2bfloat16(h);
                *(__nv_bfloat16*)(g_Ahi + off) = hh;
                *(__nv_bfloat16*)(g_Alo + off) = __float2bfloat16(h - __bfloat162float(hh));
            }
            __syncthreads();
            if (tid == 0)
                asm volatile("red.release.gpu.global.add.u32 [%0], %1;" :: "l"(&g_bar), "r"(1u) : "memory");
        }
        __syncthreads();
    }

    // ---------------- FC worker role ----------------
    unsigned* itemp = (unsigned*)(smem + S_ITEM);
    int fph[2] = {0, 0};
    for (;;) {
        __syncthreads();
        if (tid == 0) *itemp = atomicAdd(&g_fcitem, 1u);
        __syncthreads();
        unsigned item = *itemp;
        if (item >= 2048u) break;
        int s = (int)(item >> 3), dt = (int)(item & 7);

        if (tid == 0) {
            unsigned tgt = (unsigned)(NLSTM * (s + 1)), v;
            do {
                asm volatile("ld.acquire.gpu.global.u32 %0, [%1];" : "=r"(v) : "l"(&g_bar));
                if ((int)(v - tgt) >= 0) break;
                __nanosleep(64);
            } while (1);
        }
        __syncthreads();

        const unsigned char* aH = g_Ahi + (size_t)(s + 1) * SLOTP;
        const unsigned char* aL = g_Alo + (size_t)(s + 1) * SLOTP;
        const unsigned char* bH = g_FcHi + (size_t)dt * FCDP;
        const unsigned char* bL = g_FcLo + (size_t)dt * FCDP;

        // one chunk = 4 bulk copies of 18432B, CTA-wide mbarrier
        auto issueF = [&](int kc) {
            if (tid == 0) {
                int b = kc & 1;
                uint32_t mb = sb + S_MBF + b * 8;
                uint32_t d = sb + b * 73728;
                MB_EXPECT(mb, 73728);
                bulk_g2s(d,         aH + (size_t)kc * ACHP, 18432, mb);
                bulk_g2s(d + 18432, aL + (size_t)kc * ACHP, 18432, mb);
                bulk_g2s(d + 36864, bH + (size_t)kc * ACHP, 18432, mb);
                bulk_g2s(d + 55296, bL + (size_t)kc * ACHP, 18432, mb);
            }
        };

        float acc[16][4];
#pragma unroll
        for (int n = 0; n < 16; n++)
#pragma unroll
            for (int q = 0; q < 4; q++) acc[n][q] = 0.f;

        issueF(0); issueF(1);
        for (int kc = 0; kc < 16; kc++) {
            int b = kc & 1;
            MB_WAIT(sb + S_MBF + b * 8, fph[b]); fph[b] ^= 1;   // all threads
            __syncthreads();
            const unsigned char* As = smem + b * 73728;
            const unsigned char* Al = As + 18432;
            const unsigned char* Bh = As + 36864;
            const unsigned char* Bl = As + 55296;
            const int rb = (16 * w + g) * 144 + tig * 4;
#pragma unroll
            for (int ks = 0; ks < 4; ks++) {
                const int ao = rb + ks * 32;
                uint32_t ah[4], al4[4];
                ah[0] = *(const uint32_t*)(As + ao);
                ah[1] = *(const uint32_t*)(As + ao + 1152);
                ah[2] = *(const uint32_t*)(As + ao + 16);
                ah[3] = *(const uint32_t*)(As + ao + 1168);
                al4[0] = *(const uint32_t*)(Al + ao);
                al4[1] = *(const uint32_t*)(Al + ao + 1152);
                al4[2] = *(const uint32_t*)(Al + ao + 16);
                al4[3] = *(const uint32_t*)(Al + ao + 1168);
#pragma unroll
                for (int nt = 0; nt < 16; nt++) {
                    const int bo = (8 * nt + g) * 144 + tig * 4 + ks * 32;
                    uint32_t bh0 = *(const uint32_t*)(Bh + bo);
                    uint32_t bh1 = *(const uint32_t*)(Bh + bo + 16);
                    uint32_t bl0 = *(const uint32_t*)(Bl + bo);
                    uint32_t bl1 = *(const uint32_t*)(Bl + bo + 16);
                    hmma(acc[nt], ah, bh0, bh1);
                    hmma(acc[nt], al4, bh0, bh1);
                    hmma(acc[nt], ah, bl0, bl1);
                }
            }
            __syncthreads();
            if (kc + 2 < 16) issueF(kc + 2);
        }

#pragma unroll
        for (int nt = 0; nt < 16; nt++) {
            int d = dt * 128 + 8 * nt + 2 * tig;
            float2 bb = *(const float2*)(bfc + d);
            int n0 = 16 * w + g;
            float2 v0 = make_float2(acc[nt][0] + bb.x, acc[nt][1] + bb.y);
            float2 v1 = make_float2(acc[nt][2] + bb.x, acc[nt][3] + bb.y);
            *(float2*)(out + ((size_t)n0 * TT + s) * 1024 + d) = v0;
            *(float2*)(out + ((size_t)(n0 + 8) * TT + s) * 1024 + d) = v1;
        }
    }
}

// ------------------------- launch -------------------------
extern "C" void kernel_launch(void* const* d_in, const int* in_sizes, int n_in,
                              void* d_out, int out_size)
{
    const float* hT  = (const float*)d_in[0];
    const float* Wih = (const float*)d_in[1];
    const float* Whh = (const float*)d_in[2];
    const float* bih = (const float*)d_in[3];
    const float* bhh = (const float*)d_in[4];
    const float* Wfc = (const float*)d_in[5];
    const float* bfc = (const float*)d_in[6];
    float* out = (float*)d_out;

    static int total = 0;
    if (total == 0) {
        int smc = 148;
        if (cudaDeviceGetAttribute(&smc, cudaDevAttrMultiProcessorCount, 0) != cudaSuccess)
            smc = 148;
        total = smc < 129 ? 129 : (smc > 192 ? 192 : smc);
        cudaFuncSetAttribute(lstm_fused, cudaFuncAttributeMaxDynamicSharedMemorySize, SM_ALL);
    }

    prep<<<1024, 256>>>(hT, Wih, Whh, bih, bhh, Wfc);
    lstm_fused<<<total, 256, SM_ALL>>>(bfc, out);
}